// round 3
// baseline (speedup 1.0000x reference)
#include <cuda_runtime.h>
#include <cuda_bf16.h>
#include <stdint.h>

#define N_NODES 100000
#define N_EDGES 6400000
#define F_IN  16
#define F_H   8
#define F_OUT 2

// Scratch (static __device__ allocation is allowed)
__device__ float g_deg[N_NODES];
__device__ float g_dinv[N_NODES];
__device__ int   g_row[N_EDGES];
__device__ int   g_col[N_EDGES];
__device__ float g_h1[N_NODES * F_H];     // x @ W1
__device__ float g_h2[N_NODES * F_OUT];   // relu(x_emb) @ W2
__device__ int   g_is32;                  // 1 if edge_index is int32

// ---------------------------------------------------------------------------
// K0: probe edge_index dtype. If int64 (LE, values < 2^31), every odd 32-bit
// word is 0. If int32 random indices, odd words are ~always nonzero.
__global__ void k_detect(const unsigned int* __restrict__ ei_words) {
    __shared__ int any_nz;
    if (threadIdx.x == 0) any_nz = 0;
    __syncthreads();
    int nz = 0;
#pragma unroll
    for (int q = 0; q < 8; q++) {
        unsigned int wpos = 2u * (threadIdx.x + 256u * q) + 1u;  // odd words
        if (ei_words[wpos] != 0u) nz = 1;
    }
    if (nz) atomicOr(&any_nz, 1);
    __syncthreads();
    if (threadIdx.x == 0) g_is32 = any_nz;
}

// K1: init degree to 1.0 (self-loop weight)
__global__ void k_deg_init() {
    int i = blockIdx.x * blockDim.x + threadIdx.x;
    if (i < N_NODES) g_deg[i] = 1.0f;
}

// K2: degree accumulation + index extraction (dtype-adaptive)
__global__ void k_deg_edges(const void* __restrict__ ei_raw,
                            const float* __restrict__ w, int E) {
    int e = blockIdx.x * blockDim.x + threadIdx.x;
    if (e >= E) return;
    int r, c;
    if (g_is32) {
        const int* ei = (const int*)ei_raw;
        r = ei[e];
        c = ei[E + e];
    } else {
        const long long* ei = (const long long*)ei_raw;
        r = (int)ei[e];
        c = (int)ei[E + e];
    }
    g_row[e] = r;
    g_col[e] = c;
    atomicAdd(&g_deg[c], w[e]);
}

// K3: per-node — dinv, h1 = x@W1, init x_emb = dinv^2 * h1 + b1 (self loop + bias)
__global__ void k_node1(const float* __restrict__ x,
                        const float* __restrict__ W1,
                        const float* __restrict__ b1,
                        float* __restrict__ xemb) {
    __shared__ float sW[F_IN * F_H];
    __shared__ float sb[F_H];
    int t = threadIdx.x;
    if (t < F_IN * F_H) sW[t] = W1[t];
    if (t < F_H) sb[t] = b1[t];
    __syncthreads();
    int i = blockIdx.x * blockDim.x + t;
    if (i >= N_NODES) return;

    float deg = g_deg[i];
    float dinv = (deg > 0.0f) ? rsqrtf(deg) : 0.0f;
    g_dinv[i] = dinv;
    float d2 = dinv * dinv;

    float xr[F_IN];
    const float4* xp = (const float4*)(x + (size_t)i * F_IN);
#pragma unroll
    for (int q = 0; q < 4; q++) {
        float4 v = xp[q];
        xr[q * 4 + 0] = v.x; xr[q * 4 + 1] = v.y;
        xr[q * 4 + 2] = v.z; xr[q * 4 + 3] = v.w;
    }
    float h[F_H];
#pragma unroll
    for (int j = 0; j < F_H; j++) h[j] = 0.0f;
#pragma unroll
    for (int k = 0; k < F_IN; k++) {
        float xv = xr[k];
#pragma unroll
        for (int j = 0; j < F_H; j++) h[j] = fmaf(xv, sW[k * F_H + j], h[j]);
    }
    float* hp = g_h1 + (size_t)i * F_H;
    float* ep = xemb + (size_t)i * F_H;
#pragma unroll
    for (int j = 0; j < F_H; j++) {
        hp[j] = h[j];
        ep[j] = d2 * h[j] + sb[j];
    }
}

// K4: layer-1 edge scatter: xemb[col] += norm * h1[row]
__global__ void k_scat1(const float* __restrict__ w,
                        float* __restrict__ xemb, int E) {
    int e = blockIdx.x * blockDim.x + threadIdx.x;
    if (e >= E) return;
    int r = g_row[e];
    int c = g_col[e];
    float coef = g_dinv[r] * w[e] * g_dinv[c];
    const float4* hp = (const float4*)(g_h1 + (size_t)r * F_H);
    float4 a = hp[0];
    float4 b = hp[1];
    float* dst = xemb + (size_t)c * F_H;
    atomicAdd(dst + 0, coef * a.x);
    atomicAdd(dst + 1, coef * a.y);
    atomicAdd(dst + 2, coef * a.z);
    atomicAdd(dst + 3, coef * a.w);
    atomicAdd(dst + 4, coef * b.x);
    atomicAdd(dst + 5, coef * b.y);
    atomicAdd(dst + 6, coef * b.z);
    atomicAdd(dst + 7, coef * b.w);
}

// K5: per-node — h2 = relu(x_emb) @ W2, init out = dinv^2 * h2 + b2
__global__ void k_node2(const float* __restrict__ W2,
                        const float* __restrict__ b2,
                        const float* __restrict__ xemb,
                        float* __restrict__ outp) {
    __shared__ float sW[F_H * F_OUT];
    __shared__ float sb[F_OUT];
    int t = threadIdx.x;
    if (t < F_H * F_OUT) sW[t] = W2[t];
    if (t < F_OUT) sb[t] = b2[t];
    __syncthreads();
    int i = blockIdx.x * blockDim.x + t;
    if (i >= N_NODES) return;

    float dinv = g_dinv[i];
    float d2 = dinv * dinv;

    const float4* ep = (const float4*)(xemb + (size_t)i * F_H);
    float4 a = ep[0];
    float4 b = ep[1];
    float v[F_H] = {a.x, a.y, a.z, a.w, b.x, b.y, b.z, b.w};
    float h2[F_OUT] = {0.0f, 0.0f};
#pragma unroll
    for (int k = 0; k < F_H; k++) {
        float rv = fmaxf(v[k], 0.0f);
#pragma unroll
        for (int j = 0; j < F_OUT; j++) h2[j] = fmaf(rv, sW[k * F_OUT + j], h2[j]);
    }
    float* gp = g_h2 + (size_t)i * F_OUT;
    float* op = outp + (size_t)i * F_OUT;
#pragma unroll
    for (int j = 0; j < F_OUT; j++) {
        gp[j] = h2[j];
        op[j] = d2 * h2[j] + sb[j];
    }
}

// K6: layer-2 edge scatter: out[col] += norm * h2[row]
__global__ void k_scat2(const float* __restrict__ w,
                        float* __restrict__ outp, int E) {
    int e = blockIdx.x * blockDim.x + threadIdx.x;
    if (e >= E) return;
    int r = g_row[e];
    int c = g_col[e];
    float coef = g_dinv[r] * w[e] * g_dinv[c];
    const float2* hp = (const float2*)(g_h2 + (size_t)r * F_OUT);
    float2 a = hp[0];
    float* dst = outp + (size_t)c * F_OUT;
    atomicAdd(dst + 0, coef * a.x);
    atomicAdd(dst + 1, coef * a.y);
}

extern "C" void kernel_launch(void* const* d_in, const int* in_sizes, int n_in,
                              void* d_out, int out_size) {
    const float* x  = (const float*)d_in[0];
    const void*  ei = d_in[1];
    const float* w  = (const float*)d_in[2];
    const float* W1 = (const float*)d_in[3];
    const float* b1 = (const float*)d_in[4];
    const float* W2 = (const float*)d_in[5];
    const float* b2 = (const float*)d_in[6];

    int E = in_sizes[1] / 2;

    float* outp = (float*)d_out;                    // [N, 2]
    float* xemb = (float*)d_out + N_NODES * F_OUT;  // [N, 8]

    const int BT = 256;
    int nb_nodes = (N_NODES + BT - 1) / BT;
    int nb_edges = (E + BT - 1) / BT;

    k_detect<<<1, 256>>>((const unsigned int*)ei);
    k_deg_init<<<nb_nodes, BT>>>();
    k_deg_edges<<<nb_edges, BT>>>(ei, w, E);
    k_node1<<<nb_nodes, BT>>>(x, W1, b1, xemb);
    k_scat1<<<nb_edges, BT>>>(w, xemb, E);
    k_node2<<<nb_nodes, BT>>>(W2, b2, xemb, outp);
    k_scat2<<<nb_edges, BT>>>(w, outp, E);
}

// round 4
// speedup vs baseline: 1.5557x; 1.5557x over previous
#include <cuda_runtime.h>
#include <cuda_bf16.h>
#include <stdint.h>

#define N_NODES 100000
#define N_EDGES 6400000
#define F_IN  16
#define F_H   8
#define F_OUT 2

#define SCAN_BT 1024
#define NBLK ((N_NODES + SCAN_BT - 1) / SCAN_BT)   // 98

// ---- static device scratch -------------------------------------------------
__device__ float g_deg[N_NODES];
__device__ float g_dinv[N_NODES];
__device__ int   g_cnt[N_NODES];
__device__ int   g_start[N_NODES];   // CSR segment starts
__device__ int   g_cur[N_NODES];     // fill cursors
__device__ int   g_bsum[NBLK];
__device__ int   g_bsum_ex[NBLK];
__device__ float g_h1[N_NODES * F_H];
__device__ float g_h2[N_NODES * F_OUT];
__device__ int2  g_csr[N_EDGES];     // (row, bitcast coef)
__device__ int   g_is32;

// ---------------------------------------------------------------------------
// K0: dtype probe: int64 edge_index (LE, vals < 2^31) has all odd words == 0.
__global__ void k_detect(const unsigned int* __restrict__ ei_words) {
    __shared__ int any_nz;
    if (threadIdx.x == 0) any_nz = 0;
    __syncthreads();
    int nz = 0;
#pragma unroll
    for (int q = 0; q < 8; q++) {
        unsigned int wpos = 2u * (threadIdx.x + 256u * q) + 1u;
        if (ei_words[wpos] != 0u) nz = 1;
    }
    if (nz) atomicOr(&any_nz, 1);
    __syncthreads();
    if (threadIdx.x == 0) g_is32 = any_nz;
}

// K1: init deg=1 (self loop), cnt=0
__global__ void k_init() {
    int i = blockIdx.x * blockDim.x + threadIdx.x;
    if (i < N_NODES) { g_deg[i] = 1.0f; g_cnt[i] = 0; }
}

// K2: degree (weighted) + edge count per target node. Reads only col half + w.
__global__ void k_deg(const void* __restrict__ ei_raw,
                      const float* __restrict__ w, int E) {
    int e = blockIdx.x * blockDim.x + threadIdx.x;
    if (e >= E) return;
    int c;
    if (g_is32) c = ((const int*)ei_raw)[E + e];
    else        c = (int)((const long long*)ei_raw)[E + e];
    atomicAdd(&g_deg[c], w[e]);
    atomicAdd(&g_cnt[c], 1);
}

// K3: per-node dinv + h1 = x@W1
__global__ void k_node1(const float* __restrict__ x,
                        const float* __restrict__ W1) {
    __shared__ float sW[F_IN * F_H];
    int t = threadIdx.x;
    if (t < F_IN * F_H) sW[t] = W1[t];
    __syncthreads();
    int i = blockIdx.x * blockDim.x + t;
    if (i >= N_NODES) return;

    float deg = g_deg[i];
    g_dinv[i] = (deg > 0.0f) ? rsqrtf(deg) : 0.0f;

    float xr[F_IN];
    const float4* xp = (const float4*)(x + (size_t)i * F_IN);
#pragma unroll
    for (int q = 0; q < 4; q++) {
        float4 v = xp[q];
        xr[q * 4 + 0] = v.x; xr[q * 4 + 1] = v.y;
        xr[q * 4 + 2] = v.z; xr[q * 4 + 3] = v.w;
    }
    float h[F_H];
#pragma unroll
    for (int j = 0; j < F_H; j++) h[j] = 0.0f;
#pragma unroll
    for (int k = 0; k < F_IN; k++) {
        float xv = xr[k];
#pragma unroll
        for (int j = 0; j < F_H; j++) h[j] = fmaf(xv, sW[k * F_H + j], h[j]);
    }
    float4* hp = (float4*)(g_h1 + (size_t)i * F_H);
    hp[0] = make_float4(h[0], h[1], h[2], h[3]);
    hp[1] = make_float4(h[4], h[5], h[6], h[7]);
}

// K4a: per-block exclusive scan of cnt, partials into g_start, block sums out
__global__ void k_scan1() {
    __shared__ int sh[SCAN_BT];
    int tid = threadIdx.x;
    int i = blockIdx.x * SCAN_BT + tid;
    int v = (i < N_NODES) ? g_cnt[i] : 0;
    sh[tid] = v;
    __syncthreads();
#pragma unroll
    for (int d = 1; d < SCAN_BT; d <<= 1) {
        int t = (tid >= d) ? sh[tid - d] : 0;
        __syncthreads();
        sh[tid] += t;
        __syncthreads();
    }
    if (i < N_NODES) g_start[i] = sh[tid] - v;   // exclusive
    if (tid == SCAN_BT - 1) g_bsum[blockIdx.x] = sh[tid];
}

// K4b: scan the block sums (NBLK <= 128)
__global__ void k_scan2() {
    __shared__ int sh[128];
    int tid = threadIdx.x;
    int v = (tid < NBLK) ? g_bsum[tid] : 0;
    sh[tid] = v;
    __syncthreads();
#pragma unroll
    for (int d = 1; d < 128; d <<= 1) {
        int t = (tid >= d) ? sh[tid - d] : 0;
        __syncthreads();
        sh[tid] += t;
        __syncthreads();
    }
    if (tid < NBLK) g_bsum_ex[tid] = sh[tid] - v;
}

// K4c: finalize starts, init cursors
__global__ void k_scan3() {
    int i = blockIdx.x * blockDim.x + threadIdx.x;
    if (i >= N_NODES) return;
    int s = g_start[i] + g_bsum_ex[i / SCAN_BT];
    g_start[i] = s;
    g_cur[i] = s;
}

// K5: CSR fill with precomputed coefficient
__global__ void k_csr(const void* __restrict__ ei_raw,
                      const float* __restrict__ w, int E) {
    int e = blockIdx.x * blockDim.x + threadIdx.x;
    if (e >= E) return;
    int r, c;
    if (g_is32) {
        const int* ei = (const int*)ei_raw;
        r = ei[e]; c = ei[E + e];
    } else {
        const long long* ei = (const long long*)ei_raw;
        r = (int)ei[e]; c = (int)ei[E + e];
    }
    float coef = g_dinv[r] * w[e] * g_dinv[c];
    int pos = atomicAdd(&g_cur[c], 1);
    g_csr[pos] = make_int2(r, __float_as_int(coef));
}

// K6: layer-1 gather (warp per node): xemb[i] = d2*h1[i] + b1 + sum coef*h1[r]
__global__ void k_gath1(const float* __restrict__ b1,
                        float* __restrict__ xemb) {
    int gtid = blockIdx.x * blockDim.x + threadIdx.x;
    int node = gtid >> 5;
    int lane = gtid & 31;
    if (node >= N_NODES) return;

    int start = g_start[node];
    int cnt = g_cnt[node];
    float a0=0,a1=0,a2=0,a3=0,a4=0,a5=0,a6=0,a7=0;
    for (int j = lane; j < cnt; j += 32) {
        int2 pr = g_csr[start + j];
        int r = pr.x;
        float coef = __int_as_float(pr.y);
        const float4* hp = (const float4*)(g_h1 + (size_t)r * F_H);
        float4 a = hp[0];
        float4 b = hp[1];
        a0 = fmaf(coef, a.x, a0); a1 = fmaf(coef, a.y, a1);
        a2 = fmaf(coef, a.z, a2); a3 = fmaf(coef, a.w, a3);
        a4 = fmaf(coef, b.x, a4); a5 = fmaf(coef, b.y, a5);
        a6 = fmaf(coef, b.z, a6); a7 = fmaf(coef, b.w, a7);
    }
#pragma unroll
    for (int s = 16; s > 0; s >>= 1) {
        a0 += __shfl_xor_sync(0xffffffffu, a0, s);
        a1 += __shfl_xor_sync(0xffffffffu, a1, s);
        a2 += __shfl_xor_sync(0xffffffffu, a2, s);
        a3 += __shfl_xor_sync(0xffffffffu, a3, s);
        a4 += __shfl_xor_sync(0xffffffffu, a4, s);
        a5 += __shfl_xor_sync(0xffffffffu, a5, s);
        a6 += __shfl_xor_sync(0xffffffffu, a6, s);
        a7 += __shfl_xor_sync(0xffffffffu, a7, s);
    }
    if (lane == 0) {
        float dinv = g_dinv[node];
        float d2 = dinv * dinv;
        const float4* hp = (const float4*)(g_h1 + (size_t)node * F_H);
        float4 ha = hp[0];
        float4 hb = hp[1];
        float4* ep = (float4*)(xemb + (size_t)node * F_H);
        ep[0] = make_float4(a0 + d2 * ha.x + b1[0], a1 + d2 * ha.y + b1[1],
                            a2 + d2 * ha.z + b1[2], a3 + d2 * ha.w + b1[3]);
        ep[1] = make_float4(a4 + d2 * hb.x + b1[4], a5 + d2 * hb.y + b1[5],
                            a6 + d2 * hb.z + b1[6], a7 + d2 * hb.w + b1[7]);
    }
}

// K7: h2 = relu(xemb) @ W2
__global__ void k_node2(const float* __restrict__ W2,
                        const float* __restrict__ xemb) {
    __shared__ float sW[F_H * F_OUT];
    int t = threadIdx.x;
    if (t < F_H * F_OUT) sW[t] = W2[t];
    __syncthreads();
    int i = blockIdx.x * blockDim.x + t;
    if (i >= N_NODES) return;

    const float4* ep = (const float4*)(xemb + (size_t)i * F_H);
    float4 a = ep[0];
    float4 b = ep[1];
    float v[F_H] = {a.x, a.y, a.z, a.w, b.x, b.y, b.z, b.w};
    float h0 = 0.0f, h1v = 0.0f;
#pragma unroll
    for (int k = 0; k < F_H; k++) {
        float rv = fmaxf(v[k], 0.0f);
        h0 = fmaf(rv, sW[k * F_OUT + 0], h0);
        h1v = fmaf(rv, sW[k * F_OUT + 1], h1v);
    }
    float2* gp = (float2*)(g_h2 + (size_t)i * F_OUT);
    gp[0] = make_float2(h0, h1v);
}

// K8: layer-2 gather (warp per node): out[i] = d2*h2[i] + b2 + sum coef*h2[r]
__global__ void k_gath2(const float* __restrict__ b2,
                        float* __restrict__ outp) {
    int gtid = blockIdx.x * blockDim.x + threadIdx.x;
    int node = gtid >> 5;
    int lane = gtid & 31;
    if (node >= N_NODES) return;

    int start = g_start[node];
    int cnt = g_cnt[node];
    float a0 = 0.0f, a1 = 0.0f;
    for (int j = lane; j < cnt; j += 32) {
        int2 pr = g_csr[start + j];
        int r = pr.x;
        float coef = __int_as_float(pr.y);
        float2 h = *(const float2*)(g_h2 + (size_t)r * F_OUT);
        a0 = fmaf(coef, h.x, a0);
        a1 = fmaf(coef, h.y, a1);
    }
#pragma unroll
    for (int s = 16; s > 0; s >>= 1) {
        a0 += __shfl_xor_sync(0xffffffffu, a0, s);
        a1 += __shfl_xor_sync(0xffffffffu, a1, s);
    }
    if (lane == 0) {
        float dinv = g_dinv[node];
        float d2 = dinv * dinv;
        float2 h = *(const float2*)(g_h2 + (size_t)node * F_OUT);
        float2* op = (float2*)(outp + (size_t)node * F_OUT);
        op[0] = make_float2(a0 + d2 * h.x + b2[0], a1 + d2 * h.y + b2[1]);
    }
}

extern "C" void kernel_launch(void* const* d_in, const int* in_sizes, int n_in,
                              void* d_out, int out_size) {
    const float* x  = (const float*)d_in[0];
    const void*  ei = d_in[1];
    const float* w  = (const float*)d_in[2];
    const float* W1 = (const float*)d_in[3];
    const float* b1 = (const float*)d_in[4];
    const float* W2 = (const float*)d_in[5];
    const float* b2 = (const float*)d_in[6];

    int E = in_sizes[1] / 2;

    float* outp = (float*)d_out;                    // [N, 2]
    float* xemb = (float*)d_out + N_NODES * F_OUT;  // [N, 8]

    const int BT = 256;
    int nb_nodes = (N_NODES + BT - 1) / BT;
    int nb_edges = (E + BT - 1) / BT;
    int nb_warp  = (N_NODES * 32 + BT - 1) / BT;

    k_detect<<<1, 256>>>((const unsigned int*)ei);
    k_init<<<nb_nodes, BT>>>();
    k_deg<<<nb_edges, BT>>>(ei, w, E);
    k_node1<<<nb_nodes, BT>>>(x, W1);
    k_scan1<<<NBLK, SCAN_BT>>>();
    k_scan2<<<1, 128>>>();
    k_scan3<<<nb_nodes, BT>>>();
    k_csr<<<nb_edges, BT>>>(ei, w, E);
    k_gath1<<<nb_warp, BT>>>(b1, xemb);
    k_node2<<<nb_nodes, BT>>>(W2, xemb);
    k_gath2<<<nb_warp, BT>>>(b2, outp);
}

// round 5
// speedup vs baseline: 1.5577x; 1.0013x over previous
#include <cuda_runtime.h>
#include <cuda_bf16.h>
#include <stdint.h>

#define N_NODES 100000
#define N_EDGES 6400000
#define F_IN  16
#define F_H   8
#define F_OUT 2

#define SCAN_BT 1024
#define NBLK ((N_NODES + SCAN_BT - 1) / SCAN_BT)   // 98

// ---- static device scratch -------------------------------------------------
__device__ float g_deg[N_NODES];
__device__ float g_dinv[N_NODES];
__device__ int   g_cnt[N_NODES];
__device__ int   g_start[N_NODES];   // CSR segment starts
__device__ int   g_cur[N_NODES];     // fill cursors
__device__ int   g_bsum[NBLK];
__device__ int   g_bsum_ex[NBLK];
__device__ float g_h1[N_NODES * F_H];
__device__ float g_h2[N_NODES * F_OUT];
__device__ int2  g_csr[N_EDGES];     // (row, bitcast coef)
__device__ int   g_is32;

// ---------------------------------------------------------------------------
// K0: dtype probe: int64 edge_index (LE, vals < 2^31) has all odd words == 0.
__global__ void k_detect(const unsigned int* __restrict__ ei_words) {
    __shared__ int any_nz;
    if (threadIdx.x == 0) any_nz = 0;
    __syncthreads();
    int nz = 0;
#pragma unroll
    for (int q = 0; q < 8; q++) {
        unsigned int wpos = 2u * (threadIdx.x + 256u * q) + 1u;
        if (ei_words[wpos] != 0u) nz = 1;
    }
    if (nz) atomicOr(&any_nz, 1);
    __syncthreads();
    if (threadIdx.x == 0) g_is32 = any_nz;
}

// K1: init deg=1 (self loop), cnt=0
__global__ void k_init() {
    int i = blockIdx.x * blockDim.x + threadIdx.x;
    if (i < N_NODES) { g_deg[i] = 1.0f; g_cnt[i] = 0; }
}

// K2: degree (weighted) + edge count per target node. Reads only col half + w.
__global__ void k_deg(const void* __restrict__ ei_raw,
                      const float* __restrict__ w, int E) {
    int e = blockIdx.x * blockDim.x + threadIdx.x;
    if (e >= E) return;
    int c;
    if (g_is32) c = ((const int*)ei_raw)[E + e];
    else        c = (int)((const long long*)ei_raw)[E + e];
    atomicAdd(&g_deg[c], w[e]);
    atomicAdd(&g_cnt[c], 1);
}

// K3: per-node dinv + h1 = x@W1
__global__ void k_node1(const float* __restrict__ x,
                        const float* __restrict__ W1) {
    __shared__ float sW[F_IN * F_H];
    int t = threadIdx.x;
    if (t < F_IN * F_H) sW[t] = W1[t];
    __syncthreads();
    int i = blockIdx.x * blockDim.x + t;
    if (i >= N_NODES) return;

    float deg = g_deg[i];
    g_dinv[i] = (deg > 0.0f) ? rsqrtf(deg) : 0.0f;

    float xr[F_IN];
    const float4* xp = (const float4*)(x + (size_t)i * F_IN);
#pragma unroll
    for (int q = 0; q < 4; q++) {
        float4 v = xp[q];
        xr[q * 4 + 0] = v.x; xr[q * 4 + 1] = v.y;
        xr[q * 4 + 2] = v.z; xr[q * 4 + 3] = v.w;
    }
    float h[F_H];
#pragma unroll
    for (int j = 0; j < F_H; j++) h[j] = 0.0f;
#pragma unroll
    for (int k = 0; k < F_IN; k++) {
        float xv = xr[k];
#pragma unroll
        for (int j = 0; j < F_H; j++) h[j] = fmaf(xv, sW[k * F_H + j], h[j]);
    }
    float4* hp = (float4*)(g_h1 + (size_t)i * F_H);
    hp[0] = make_float4(h[0], h[1], h[2], h[3]);
    hp[1] = make_float4(h[4], h[5], h[6], h[7]);
}

// K4a: per-block exclusive scan of cnt, partials into g_start, block sums out
__global__ void k_scan1() {
    __shared__ int sh[SCAN_BT];
    int tid = threadIdx.x;
    int i = blockIdx.x * SCAN_BT + tid;
    int v = (i < N_NODES) ? g_cnt[i] : 0;
    sh[tid] = v;
    __syncthreads();
#pragma unroll
    for (int d = 1; d < SCAN_BT; d <<= 1) {
        int t = (tid >= d) ? sh[tid - d] : 0;
        __syncthreads();
        sh[tid] += t;
        __syncthreads();
    }
    if (i < N_NODES) g_start[i] = sh[tid] - v;   // exclusive
    if (tid == SCAN_BT - 1) g_bsum[blockIdx.x] = sh[tid];
}

// K4b: scan the block sums (NBLK <= 128)
__global__ void k_scan2() {
    __shared__ int sh[128];
    int tid = threadIdx.x;
    int v = (tid < NBLK) ? g_bsum[tid] : 0;
    sh[tid] = v;
    __syncthreads();
#pragma unroll
    for (int d = 1; d < 128; d <<= 1) {
        int t = (tid >= d) ? sh[tid - d] : 0;
        __syncthreads();
        sh[tid] += t;
        __syncthreads();
    }
    if (tid < NBLK) g_bsum_ex[tid] = sh[tid] - v;
}

// K4c: finalize starts, init cursors
__global__ void k_scan3() {
    int i = blockIdx.x * blockDim.x + threadIdx.x;
    if (i >= N_NODES) return;
    int s = g_start[i] + g_bsum_ex[i / SCAN_BT];
    g_start[i] = s;
    g_cur[i] = s;
}

// K5: CSR fill with precomputed coefficient
__global__ void k_csr(const void* __restrict__ ei_raw,
                      const float* __restrict__ w, int E) {
    int e = blockIdx.x * blockDim.x + threadIdx.x;
    if (e >= E) return;
    int r, c;
    if (g_is32) {
        const int* ei = (const int*)ei_raw;
        r = ei[e]; c = ei[E + e];
    } else {
        const long long* ei = (const long long*)ei_raw;
        r = (int)ei[e]; c = (int)ei[E + e];
    }
    float coef = g_dinv[r] * w[e] * g_dinv[c];
    int pos = atomicAdd(&g_cur[c], 1);
    g_csr[pos] = make_int2(r, __float_as_int(coef));
}

// K6: layer-1 gather (warp per node): xemb[i] = d2*h1[i] + b1 + sum coef*h1[r]
__global__ void k_gath1(const float* __restrict__ b1,
                        float* __restrict__ xemb) {
    int gtid = blockIdx.x * blockDim.x + threadIdx.x;
    int node = gtid >> 5;
    int lane = gtid & 31;
    if (node >= N_NODES) return;

    int start = g_start[node];
    int cnt = g_cnt[node];
    float a0=0,a1=0,a2=0,a3=0,a4=0,a5=0,a6=0,a7=0;
    for (int j = lane; j < cnt; j += 32) {
        int2 pr = g_csr[start + j];
        int r = pr.x;
        float coef = __int_as_float(pr.y);
        const float4* hp = (const float4*)(g_h1 + (size_t)r * F_H);
        float4 a = hp[0];
        float4 b = hp[1];
        a0 = fmaf(coef, a.x, a0); a1 = fmaf(coef, a.y, a1);
        a2 = fmaf(coef, a.z, a2); a3 = fmaf(coef, a.w, a3);
        a4 = fmaf(coef, b.x, a4); a5 = fmaf(coef, b.y, a5);
        a6 = fmaf(coef, b.z, a6); a7 = fmaf(coef, b.w, a7);
    }
#pragma unroll
    for (int s = 16; s > 0; s >>= 1) {
        a0 += __shfl_xor_sync(0xffffffffu, a0, s);
        a1 += __shfl_xor_sync(0xffffffffu, a1, s);
        a2 += __shfl_xor_sync(0xffffffffu, a2, s);
        a3 += __shfl_xor_sync(0xffffffffu, a3, s);
        a4 += __shfl_xor_sync(0xffffffffu, a4, s);
        a5 += __shfl_xor_sync(0xffffffffu, a5, s);
        a6 += __shfl_xor_sync(0xffffffffu, a6, s);
        a7 += __shfl_xor_sync(0xffffffffu, a7, s);
    }
    if (lane == 0) {
        float dinv = g_dinv[node];
        float d2 = dinv * dinv;
        const float4* hp = (const float4*)(g_h1 + (size_t)node * F_H);
        float4 ha = hp[0];
        float4 hb = hp[1];
        float4* ep = (float4*)(xemb + (size_t)node * F_H);
        ep[0] = make_float4(a0 + d2 * ha.x + b1[0], a1 + d2 * ha.y + b1[1],
                            a2 + d2 * ha.z + b1[2], a3 + d2 * ha.w + b1[3]);
        ep[1] = make_float4(a4 + d2 * hb.x + b1[4], a5 + d2 * hb.y + b1[5],
                            a6 + d2 * hb.z + b1[6], a7 + d2 * hb.w + b1[7]);
    }
}

// K7: h2 = relu(xemb) @ W2
__global__ void k_node2(const float* __restrict__ W2,
                        const float* __restrict__ xemb) {
    __shared__ float sW[F_H * F_OUT];
    int t = threadIdx.x;
    if (t < F_H * F_OUT) sW[t] = W2[t];
    __syncthreads();
    int i = blockIdx.x * blockDim.x + t;
    if (i >= N_NODES) return;

    const float4* ep = (const float4*)(xemb + (size_t)i * F_H);
    float4 a = ep[0];
    float4 b = ep[1];
    float v[F_H] = {a.x, a.y, a.z, a.w, b.x, b.y, b.z, b.w};
    float h0 = 0.0f, h1v = 0.0f;
#pragma unroll
    for (int k = 0; k < F_H; k++) {
        float rv = fmaxf(v[k], 0.0f);
        h0 = fmaf(rv, sW[k * F_OUT + 0], h0);
        h1v = fmaf(rv, sW[k * F_OUT + 1], h1v);
    }
    float2* gp = (float2*)(g_h2 + (size_t)i * F_OUT);
    gp[0] = make_float2(h0, h1v);
}

// K8: layer-2 gather (warp per node): out[i] = d2*h2[i] + b2 + sum coef*h2[r]
__global__ void k_gath2(const float* __restrict__ b2,
                        float* __restrict__ outp) {
    int gtid = blockIdx.x * blockDim.x + threadIdx.x;
    int node = gtid >> 5;
    int lane = gtid & 31;
    if (node >= N_NODES) return;

    int start = g_start[node];
    int cnt = g_cnt[node];
    float a0 = 0.0f, a1 = 0.0f;
    for (int j = lane; j < cnt; j += 32) {
        int2 pr = g_csr[start + j];
        int r = pr.x;
        float coef = __int_as_float(pr.y);
        float2 h = *(const float2*)(g_h2 + (size_t)r * F_OUT);
        a0 = fmaf(coef, h.x, a0);
        a1 = fmaf(coef, h.y, a1);
    }
#pragma unroll
    for (int s = 16; s > 0; s >>= 1) {
        a0 += __shfl_xor_sync(0xffffffffu, a0, s);
        a1 += __shfl_xor_sync(0xffffffffu, a1, s);
    }
    if (lane == 0) {
        float dinv = g_dinv[node];
        float d2 = dinv * dinv;
        float2 h = *(const float2*)(g_h2 + (size_t)node * F_OUT);
        float2* op = (float2*)(outp + (size_t)node * F_OUT);
        op[0] = make_float2(a0 + d2 * h.x + b2[0], a1 + d2 * h.y + b2[1]);
    }
}

extern "C" void kernel_launch(void* const* d_in, const int* in_sizes, int n_in,
                              void* d_out, int out_size) {
    const float* x  = (const float*)d_in[0];
    const void*  ei = d_in[1];
    const float* w  = (const float*)d_in[2];
    const float* W1 = (const float*)d_in[3];
    const float* b1 = (const float*)d_in[4];
    const float* W2 = (const float*)d_in[5];
    const float* b2 = (const float*)d_in[6];

    int E = in_sizes[1] / 2;

    float* outp = (float*)d_out;                    // [N, 2]
    float* xemb = (float*)d_out + N_NODES * F_OUT;  // [N, 8]

    const int BT = 256;
    int nb_nodes = (N_NODES + BT - 1) / BT;
    int nb_edges = (E + BT - 1) / BT;
    int nb_warp  = (N_NODES * 32 + BT - 1) / BT;

    k_detect<<<1, 256>>>((const unsigned int*)ei);
    k_init<<<nb_nodes, BT>>>();
    k_deg<<<nb_edges, BT>>>(ei, w, E);
    k_node1<<<nb_nodes, BT>>>(x, W1);
    k_scan1<<<NBLK, SCAN_BT>>>();
    k_scan2<<<1, 128>>>();
    k_scan3<<<nb_nodes, BT>>>();
    k_csr<<<nb_edges, BT>>>(ei, w, E);
    k_gath1<<<nb_warp, BT>>>(b1, xemb);
    k_node2<<<nb_nodes, BT>>>(W2, xemb);
    k_gath2<<<nb_warp, BT>>>(b2, outp);
}

// round 6
// speedup vs baseline: 1.7374x; 1.1154x over previous
#include <cuda_runtime.h>
#include <cuda_bf16.h>
#include <stdint.h>

#define N_NODES 100000
#define N_EDGES 6400000
#define F_IN  16
#define F_H   8
#define F_OUT 2

#define SCAN_BT 1024
#define NBLK ((N_NODES + SCAN_BT - 1) / SCAN_BT)   // 98

// ---- static device scratch -------------------------------------------------
__device__ float g_dinv[N_NODES];
__device__ int   g_cnt[N_NODES];
__device__ int   g_start[N_NODES + 1];
__device__ int   g_cur[N_NODES];
__device__ int   g_bsum[NBLK];
__device__ int   g_bsum_ex[NBLK];
__device__ float g_h1[N_NODES * F_H];     // dinv * (x @ W1)
__device__ float g_h2[N_NODES * F_OUT];   // dinv * (relu(xemb) @ W2)
__device__ int2  g_csr[N_EDGES];          // (row, bitcast w)
__device__ int   g_is32;

// ---------------------------------------------------------------------------
// K0: dtype probe: int64 edge_index (LE, vals < 2^31) has all odd words == 0.
__global__ void k_detect(const unsigned int* __restrict__ ei_words) {
    __shared__ int any_nz;
    if (threadIdx.x == 0) any_nz = 0;
    __syncthreads();
    int nz = 0;
#pragma unroll
    for (int q = 0; q < 8; q++) {
        unsigned int wpos = 2u * (threadIdx.x + 256u * q) + 1u;
        if (ei_words[wpos] != 0u) nz = 1;
    }
    if (nz) atomicOr(&any_nz, 1);
    __syncthreads();
    if (threadIdx.x == 0) g_is32 = any_nz;
}

// K1: zero counts
__global__ void k_zero() {
    int i = blockIdx.x * blockDim.x + threadIdx.x;
    if (i < N_NODES) g_cnt[i] = 0;
}

// K2: per-target edge counts (reads ONLY the col half; int4-vectorized)
__global__ void k_cnt(const void* __restrict__ ei_raw, int E) {
    int base = (blockIdx.x * blockDim.x + threadIdx.x) * 4;
    if (base >= E) return;
    if (g_is32) {
        const int* col = (const int*)ei_raw + E;
        if (base + 3 < E) {
            int4 c4 = *(const int4*)(col + base);
            atomicAdd(&g_cnt[c4.x], 1);
            atomicAdd(&g_cnt[c4.y], 1);
            atomicAdd(&g_cnt[c4.z], 1);
            atomicAdd(&g_cnt[c4.w], 1);
        } else {
            for (int e = base; e < E; e++) atomicAdd(&g_cnt[col[e]], 1);
        }
    } else {
        const long long* col = (const long long*)ei_raw + E;
        int hi = (base + 4 < E) ? base + 4 : E;
        for (int e = base; e < hi; e++) atomicAdd(&g_cnt[(int)col[e]], 1);
    }
}

// K3a: per-block exclusive scan of cnt
__global__ void k_scan1() {
    __shared__ int sh[SCAN_BT];
    int tid = threadIdx.x;
    int i = blockIdx.x * SCAN_BT + tid;
    int v = (i < N_NODES) ? g_cnt[i] : 0;
    sh[tid] = v;
    __syncthreads();
#pragma unroll
    for (int d = 1; d < SCAN_BT; d <<= 1) {
        int t = (tid >= d) ? sh[tid - d] : 0;
        __syncthreads();
        sh[tid] += t;
        __syncthreads();
    }
    if (i < N_NODES) g_start[i] = sh[tid] - v;   // exclusive partial
    if (tid == SCAN_BT - 1) g_bsum[blockIdx.x] = sh[tid];
}

// K3b: scan block sums (NBLK <= 128)
__global__ void k_scan2() {
    __shared__ int sh[128];
    int tid = threadIdx.x;
    int v = (tid < NBLK) ? g_bsum[tid] : 0;
    sh[tid] = v;
    __syncthreads();
#pragma unroll
    for (int d = 1; d < 128; d <<= 1) {
        int t = (tid >= d) ? sh[tid - d] : 0;
        __syncthreads();
        sh[tid] += t;
        __syncthreads();
    }
    if (tid < NBLK) g_bsum_ex[tid] = sh[tid] - v;
}

// K3c: finalize starts, init cursors, sentinel
__global__ void k_scan3(int E) {
    int i = blockIdx.x * blockDim.x + threadIdx.x;
    if (i == 0) g_start[N_NODES] = E;
    if (i >= N_NODES) return;
    int s = g_start[i] + g_bsum_ex[i / SCAN_BT];
    g_start[i] = s;
    g_cur[i] = s;
}

// K4: CSR fill with raw (row, weight) — no dinv gathers here
__global__ void k_fill(const void* __restrict__ ei_raw,
                       const float* __restrict__ w, int E) {
    int e = blockIdx.x * blockDim.x + threadIdx.x;
    if (e >= E) return;
    int r, c;
    if (g_is32) {
        const int* ei = (const int*)ei_raw;
        r = ei[e]; c = ei[E + e];
    } else {
        const long long* ei = (const long long*)ei_raw;
        r = (int)ei[e]; c = (int)ei[E + e];
    }
    int pos = atomicAdd(&g_cur[c], 1);
    g_csr[pos] = make_int2(r, __float_as_int(w[e]));
}

// K5: segment-sum weighted degree from CSR (no atomics): dinv = rsqrt(1 + sum w)
__global__ void k_segdeg() {
    int gtid = blockIdx.x * blockDim.x + threadIdx.x;
    int node = gtid >> 5;
    int lane = gtid & 31;
    if (node >= N_NODES) return;
    int s = g_start[node];
    int t = g_start[node + 1];
    float acc = 0.0f;
    for (int j = s + lane; j < t; j += 32) acc += __int_as_float(g_csr[j].y);
#pragma unroll
    for (int d = 16; d > 0; d >>= 1) acc += __shfl_xor_sync(0xffffffffu, acc, d);
    if (lane == 0) g_dinv[node] = rsqrtf(1.0f + acc);
}

// K6: h1' = dinv * (x @ W1)
__global__ void k_node1(const float* __restrict__ x,
                        const float* __restrict__ W1) {
    __shared__ float sW[F_IN * F_H];
    int t = threadIdx.x;
    if (t < F_IN * F_H) sW[t] = W1[t];
    __syncthreads();
    int i = blockIdx.x * blockDim.x + t;
    if (i >= N_NODES) return;

    float dinv = g_dinv[i];
    float xr[F_IN];
    const float4* xp = (const float4*)(x + (size_t)i * F_IN);
#pragma unroll
    for (int q = 0; q < 4; q++) {
        float4 v = xp[q];
        xr[q * 4 + 0] = v.x; xr[q * 4 + 1] = v.y;
        xr[q * 4 + 2] = v.z; xr[q * 4 + 3] = v.w;
    }
    float h[F_H];
#pragma unroll
    for (int j = 0; j < F_H; j++) h[j] = 0.0f;
#pragma unroll
    for (int k = 0; k < F_IN; k++) {
        float xv = xr[k];
#pragma unroll
        for (int j = 0; j < F_H; j++) h[j] = fmaf(xv, sW[k * F_H + j], h[j]);
    }
    float4* hp = (float4*)(g_h1 + (size_t)i * F_H);
    hp[0] = make_float4(dinv * h[0], dinv * h[1], dinv * h[2], dinv * h[3]);
    hp[1] = make_float4(dinv * h[4], dinv * h[5], dinv * h[6], dinv * h[7]);
}

// K7: layer-1 gather: xemb[c] = dinv[c]*(sum_e w*h1'[r] + h1'[c]) + b1
__global__ void k_gath1(const float* __restrict__ b1,
                        float* __restrict__ xemb) {
    int gtid = blockIdx.x * blockDim.x + threadIdx.x;
    int node = gtid >> 5;
    int lane = gtid & 31;
    if (node >= N_NODES) return;

    int s = g_start[node];
    int t = g_start[node + 1];
    float a0=0,a1=0,a2=0,a3=0,a4=0,a5=0,a6=0,a7=0;
    for (int j = s + lane; j < t; j += 32) {
        int2 pr = g_csr[j];
        int r = pr.x;
        float wv = __int_as_float(pr.y);
        const float4* hp = (const float4*)(g_h1 + (size_t)r * F_H);
        float4 a = hp[0];
        float4 b = hp[1];
        a0 = fmaf(wv, a.x, a0); a1 = fmaf(wv, a.y, a1);
        a2 = fmaf(wv, a.z, a2); a3 = fmaf(wv, a.w, a3);
        a4 = fmaf(wv, b.x, a4); a5 = fmaf(wv, b.y, a5);
        a6 = fmaf(wv, b.z, a6); a7 = fmaf(wv, b.w, a7);
    }
#pragma unroll
    for (int d = 16; d > 0; d >>= 1) {
        a0 += __shfl_xor_sync(0xffffffffu, a0, d);
        a1 += __shfl_xor_sync(0xffffffffu, a1, d);
        a2 += __shfl_xor_sync(0xffffffffu, a2, d);
        a3 += __shfl_xor_sync(0xffffffffu, a3, d);
        a4 += __shfl_xor_sync(0xffffffffu, a4, d);
        a5 += __shfl_xor_sync(0xffffffffu, a5, d);
        a6 += __shfl_xor_sync(0xffffffffu, a6, d);
        a7 += __shfl_xor_sync(0xffffffffu, a7, d);
    }
    if (lane == 0) {
        float dinv = g_dinv[node];
        const float4* hp = (const float4*)(g_h1 + (size_t)node * F_H);
        float4 ha = hp[0];
        float4 hb = hp[1];
        float4* ep = (float4*)(xemb + (size_t)node * F_H);
        ep[0] = make_float4(dinv * (a0 + ha.x) + b1[0], dinv * (a1 + ha.y) + b1[1],
                            dinv * (a2 + ha.z) + b1[2], dinv * (a3 + ha.w) + b1[3]);
        ep[1] = make_float4(dinv * (a4 + hb.x) + b1[4], dinv * (a5 + hb.y) + b1[5],
                            dinv * (a6 + hb.z) + b1[6], dinv * (a7 + hb.w) + b1[7]);
    }
}

// K8: h2' = dinv * (relu(xemb) @ W2)
__global__ void k_node2(const float* __restrict__ W2,
                        const float* __restrict__ xemb) {
    __shared__ float sW[F_H * F_OUT];
    int t = threadIdx.x;
    if (t < F_H * F_OUT) sW[t] = W2[t];
    __syncthreads();
    int i = blockIdx.x * blockDim.x + t;
    if (i >= N_NODES) return;

    float dinv = g_dinv[i];
    const float4* ep = (const float4*)(xemb + (size_t)i * F_H);
    float4 a = ep[0];
    float4 b = ep[1];
    float v[F_H] = {a.x, a.y, a.z, a.w, b.x, b.y, b.z, b.w};
    float h0 = 0.0f, h1v = 0.0f;
#pragma unroll
    for (int k = 0; k < F_H; k++) {
        float rv = fmaxf(v[k], 0.0f);
        h0 = fmaf(rv, sW[k * F_OUT + 0], h0);
        h1v = fmaf(rv, sW[k * F_OUT + 1], h1v);
    }
    float2* gp = (float2*)(g_h2 + (size_t)i * F_OUT);
    gp[0] = make_float2(dinv * h0, dinv * h1v);
}

// K9: layer-2 gather: out[c] = dinv[c]*(sum_e w*h2'[r] + h2'[c]) + b2
__global__ void k_gath2(const float* __restrict__ b2,
                        float* __restrict__ outp) {
    int gtid = blockIdx.x * blockDim.x + threadIdx.x;
    int node = gtid >> 5;
    int lane = gtid & 31;
    if (node >= N_NODES) return;

    int s = g_start[node];
    int t = g_start[node + 1];
    float a0 = 0.0f, a1 = 0.0f;
    for (int j = s + lane; j < t; j += 32) {
        int2 pr = g_csr[j];
        float wv = __int_as_float(pr.y);
        float2 h = *(const float2*)(g_h2 + (size_t)pr.x * F_OUT);
        a0 = fmaf(wv, h.x, a0);
        a1 = fmaf(wv, h.y, a1);
    }
#pragma unroll
    for (int d = 16; d > 0; d >>= 1) {
        a0 += __shfl_xor_sync(0xffffffffu, a0, d);
        a1 += __shfl_xor_sync(0xffffffffu, a1, d);
    }
    if (lane == 0) {
        float dinv = g_dinv[node];
        float2 h = *(const float2*)(g_h2 + (size_t)node * F_OUT);
        float2* op = (float2*)(outp + (size_t)node * F_OUT);
        op[0] = make_float2(dinv * (a0 + h.x) + b2[0], dinv * (a1 + h.y) + b2[1]);
    }
}

extern "C" void kernel_launch(void* const* d_in, const int* in_sizes, int n_in,
                              void* d_out, int out_size) {
    const float* x  = (const float*)d_in[0];
    const void*  ei = d_in[1];
    const float* w  = (const float*)d_in[2];
    const float* W1 = (const float*)d_in[3];
    const float* b1 = (const float*)d_in[4];
    const float* W2 = (const float*)d_in[5];
    const float* b2 = (const float*)d_in[6];

    int E = in_sizes[1] / 2;

    float* outp = (float*)d_out;                    // [N, 2]
    float* xemb = (float*)d_out + N_NODES * F_OUT;  // [N, 8]

    const int BT = 256;
    int nb_nodes = (N_NODES + BT - 1) / BT;
    int nb_edges = (E + BT - 1) / BT;
    int nb_cnt   = ((E + 3) / 4 + BT - 1) / BT;
    int nb_warp  = (N_NODES * 32 + BT - 1) / BT;

    k_detect<<<1, 256>>>((const unsigned int*)ei);
    k_zero<<<nb_nodes, BT>>>();
    k_cnt<<<nb_cnt, BT>>>(ei, E);
    k_scan1<<<NBLK, SCAN_BT>>>();
    k_scan2<<<1, 128>>>();
    k_scan3<<<nb_nodes, BT>>>(E);
    k_fill<<<nb_edges, BT>>>(ei, w, E);
    k_segdeg<<<nb_warp, BT>>>();
    k_node1<<<nb_nodes, BT>>>(x, W1);
    k_gath1<<<nb_warp, BT>>>(b1, xemb);
    k_node2<<<nb_nodes, BT>>>(W2, xemb);
    k_gath2<<<nb_warp, BT>>>(b2, outp);
}